// round 1
// baseline (speedup 1.0000x reference)
#include <cuda_runtime.h>

#define D      4096
#define BROWS  4096
#define NPACK  32      // f32x2 packs per thread (64 floats)
#define GT     64      // threads per group (2 warps) -> one row
#define GROUPS 4       // groups per CTA (256 threads)
#define CTAS   296     // 2 CTAs per SM on 148 SMs

typedef unsigned long long ull;

// u = g_mu + softplus(g_rho) * epsilon, computed once per launch
__device__ float g_u[D];

// ---------- packed f32x2 helpers (sm_103a) ----------
__device__ __forceinline__ ull pk2(float lo, float hi) {
    ull r; asm("mov.b64 %0, {%1, %2};" : "=l"(r) : "f"(lo), "f"(hi)); return r;
}
__device__ __forceinline__ void upk(ull p, float& lo, float& hi) {
    asm("mov.b64 {%0, %1}, %2;" : "=f"(lo), "=f"(hi) : "l"(p));
}
__device__ __forceinline__ ull padd(ull a, ull b) {
    ull r; asm("add.rn.f32x2 %0, %1, %2;" : "=l"(r) : "l"(a), "l"(b)); return r;
}
__device__ __forceinline__ ull pmul(ull a, ull b) {
    ull r; asm("mul.rn.f32x2 %0, %1, %2;" : "=l"(r) : "l"(a), "l"(b)); return r;
}
__device__ __forceinline__ ull pfma(ull a, ull b, ull c) {  // a*b + c
    ull r; asm("fma.rn.f32x2 %0, %1, %2, %3;" : "=l"(r) : "l"(a), "l"(b), "l"(c)); return r;
}

#define POS1 0x3F8000003F800000ull
#define NEG1 0xBF800000BF800000ull

__device__ __forceinline__ ull psub(ull a, ull b) {  // a - b
    return pfma(b, NEG1, a);
}

// ---------- u precompute ----------
__global__ void compute_u_kernel(const float* __restrict__ eps,
                                 const float* __restrict__ g_mu,
                                 const float* __restrict__ g_rho) {
    int i = blockIdx.x * blockDim.x + threadIdx.x;
    if (i < D) {
        float r  = g_rho[i];
        float sp = fmaxf(r, 0.0f) + log1pf(expf(-fabsf(r)));  // softplus, stable
        g_u[i]   = fmaf(sp, eps[i], g_mu[i]);
    }
}

// ---------- FWHT over 4096 elements held by one 64-thread group ----------
// Element index: i = a*64 + t, a in [64), t = group-local tid in [64).
// a = 2j + a0: a0 = pack lane, j = register index.
// t = w*32 + l: w = warp-within-group bit, l = lane.
// Stages (commuting bit-butterflies, natural-order Hadamard):
//   H_2(a0) in-pack, H_32(j) packed regs, H_32(l) shfl_xor, H_2(w) smem exchange.
__device__ __forceinline__ void fwht4096(ull v[NPACK], int t, int l, ull sgnw, ull* exg) {
    // H_2 over pack lanes (a0)
    #pragma unroll
    for (int j = 0; j < NPACK; j++) {
        float lo, hi; upk(v[j], lo, hi);
        v[j] = pk2(lo + hi, lo - hi);
    }
    // H_32 over register index j (packed butterflies)
    #pragma unroll
    for (int m = 1; m < 32; m <<= 1) {
        #pragma unroll
        for (int j = 0; j < NPACK; j++) {
            if (!(j & m)) {
                ull a = v[j], b = v[j | m];
                v[j]     = padd(a, b);
                v[j | m] = psub(a, b);
            }
        }
    }
    // H_32 over lanes: v = v*sign + shuffled_partner (sign = -1 iff (l&m))
    #pragma unroll
    for (int m = 1; m < 32; m <<= 1) {
        ull sg = (l & m) ? NEG1 : POS1;
        #pragma unroll
        for (int j = 0; j < NPACK; j++) {
            float lo, hi; upk(v[j], lo, hi);
            float plo = __shfl_xor_sync(0xffffffffu, lo, m);
            float phi = __shfl_xor_sync(0xffffffffu, hi, m);
            v[j] = pfma(v[j], sg, pk2(plo, phi));
        }
    }
    // H_2 across the two warps of the group via smem exchange
    __syncthreads();   // prior reads of exg complete (prev FWHT / prev row)
    #pragma unroll
    for (int j = 0; j < NPACK; j++) exg[(j << 6) + t] = v[j];
    __syncthreads();
    const int tp = t ^ 32;
    #pragma unroll
    for (int j = 0; j < NPACK; j++) {
        ull q = exg[(j << 6) + tp];
        v[j] = pfma(v[j], sgnw, q);   // w=0: own+partner, w=1: partner-own
    }
}

// ---------- main kernel: y[row,:] = s1 (.) H (u (.) H (s2 (.) x[row,:])) ----------
__global__ void __launch_bounds__(256, 2)
whvi_kernel(const float* __restrict__ x,
            const float* __restrict__ s1,
            const float* __restrict__ s2,
            float* __restrict__ y) {
    extern __shared__ ull sm[];
    ull* ex  = sm;                   // GROUPS * 2048 packs (64KB exchange)
    ull* s2p = sm + GROUPS * 2048;   // 2048 packs (16KB)
    ull* up  = s2p + 2048;
    ull* s1p = up  + 2048;

    const int tid = threadIdx.x;

    // Pack the three diagonal vectors into smem once per CTA.
    // pack[j*64+t] = (vec[j*128+t], vec[j*128+64+t])  (pairs a=2j, a=2j+1)
    #pragma unroll
    for (int idx = tid; idx < 2048; idx += 256) {
        int j = idx >> 6, t = idx & 63;
        int b = j * 128 + t;
        s2p[idx] = pk2(s2[b],  s2[b + 64]);
        up[idx]  = pk2(g_u[b], g_u[b + 64]);
        s1p[idx] = pk2(s1[b],  s1[b + 64]);
    }
    __syncthreads();

    const int g = tid >> 6;        // group id
    const int t = tid & 63;        // group-local thread
    const int l = t & 31;          // lane
    ull* exg = ex + g * 2048;
    const ull sgnw = (t & 32) ? NEG1 : POS1;

    // 1024 row-blocks (4 rows each), strided across 296 CTAs (load-balanced)
    for (int rb = blockIdx.x; rb < (BROWS / GROUPS); rb += CTAS) {
        const int row = rb * GROUPS + g;
        const float* __restrict__ xr = x + (size_t)row * D;
        float* __restrict__ yr = y + (size_t)row * D;

        ull v[NPACK];
        #pragma unroll
        for (int j = 0; j < NPACK; j++) {
            int b = j * 128 + t;
            v[j] = pmul(pk2(xr[b], xr[b + 64]), s2p[(j << 6) + t]);
        }

        fwht4096(v, t, l, sgnw, exg);

        #pragma unroll
        for (int j = 0; j < NPACK; j++) v[j] = pmul(v[j], up[(j << 6) + t]);

        fwht4096(v, t, l, sgnw, exg);

        #pragma unroll
        for (int j = 0; j < NPACK; j++) {
            ull r = pmul(v[j], s1p[(j << 6) + t]);
            float lo, hi; upk(r, lo, hi);
            int b = j * 128 + t;
            yr[b]      = lo;
            yr[b + 64] = hi;
        }
    }
}

extern "C" void kernel_launch(void* const* d_in, const int* in_sizes, int n_in,
                              void* d_out, int out_size) {
    const float* x    = (const float*)d_in[0];
    const float* eps  = (const float*)d_in[1];
    const float* s1   = (const float*)d_in[2];
    const float* s2   = (const float*)d_in[3];
    const float* gmu  = (const float*)d_in[4];
    const float* grho = (const float*)d_in[5];
    float* y = (float*)d_out;

    compute_u_kernel<<<D / 256, 256>>>(eps, gmu, grho);

    const size_t smem = (GROUPS * 2048 + 3 * 2048) * sizeof(ull);  // 114688 B
    cudaFuncSetAttribute(whvi_kernel,
                         cudaFuncAttributeMaxDynamicSharedMemorySize, (int)smem);
    whvi_kernel<<<CTAS, 256, smem>>>(x, s1, s2, y);
}

// round 7
// speedup vs baseline: 1.2513x; 1.2513x over previous
#include <cuda_runtime.h>

#define D      4096
#define BROWS  4096
#define NPACK  32      // f32x2 packs per thread (64 floats)
#define GROUPS 4       // 64-thread groups per 256-thread CTA
#define CTAS   296     // 2 CTAs per SM on 148 SMs

typedef unsigned long long ull;

// u = g_mu + softplus(g_rho) * epsilon
__device__ float g_u[D];

// ---------- packed f32x2 helpers ----------
__device__ __forceinline__ ull pk2(float lo, float hi) {
    ull r; asm("mov.b64 %0, {%1, %2};" : "=l"(r) : "f"(lo), "f"(hi)); return r;
}
__device__ __forceinline__ void upk(ull p, float& lo, float& hi) {
    asm("mov.b64 {%0, %1}, %2;" : "=f"(lo), "=f"(hi) : "l"(p));
}
__device__ __forceinline__ ull padd(ull a, ull b) {
    ull r; asm("add.rn.f32x2 %0, %1, %2;" : "=l"(r) : "l"(a), "l"(b)); return r;
}
__device__ __forceinline__ ull pmul(ull a, ull b) {
    ull r; asm("mul.rn.f32x2 %0, %1, %2;" : "=l"(r) : "l"(a), "l"(b)); return r;
}
__device__ __forceinline__ ull pfma(ull a, ull b, ull c) {
    ull r; asm("fma.rn.f32x2 %0, %1, %2, %3;" : "=l"(r) : "l"(a), "l"(b), "l"(c)); return r;
}
#define NEG1 0xBF800000BF800000ull
__device__ __forceinline__ ull psub(ull a, ull b) { return pfma(b, NEG1, a); }

// per-group named barrier (64 threads)
__device__ __forceinline__ void gbar(int id) {
    asm volatile("bar.sync %0, 64;" :: "r"(id) : "memory");
}

// ---------- u precompute ----------
__global__ void compute_u_kernel(const float* __restrict__ eps,
                                 const float* __restrict__ g_mu,
                                 const float* __restrict__ g_rho) {
    int i = blockIdx.x * blockDim.x + threadIdx.x;
    if (i < D) {
        float r  = g_rho[i];
        float sp = fmaxf(r, 0.0f) + log1pf(expf(-fabsf(r)));
        g_u[i]   = fmaf(sp, eps[i], g_mu[i]);
    }
}

// ---------- in-register FWHT over the 6 slot bits ----------
// slot rho = 2j + a0: scalar butterfly over pack bit, packed butterflies over j.
__device__ __forceinline__ void fwht64(ull v[NPACK]) {
    #pragma unroll
    for (int j = 0; j < NPACK; j++) {
        float lo, hi; upk(v[j], lo, hi);
        v[j] = pk2(lo + hi, lo - hi);
    }
    #pragma unroll
    for (int m = 1; m < 32; m <<= 1) {
        #pragma unroll
        for (int j = 0; j < NPACK; j++) {
            if (!(j & m)) {
                ull a = v[j], b = v[j | m];
                v[j]     = padd(a, b);
                v[j | m] = psub(a, b);
            }
        }
    }
}

// ---------- 64x64 transpose within a group via swizzled smem ----------
// Write: value (thread t, float-slot rho) -> S[rho*64 + 2*((t>>1)^(rho&31)) + (t&1)]
// Read:  thread t, new pack j = (old threads 2j, 2j+1) at old slot t:
//        ull load at S_ull[t*32 + (j ^ (t&31))]  (lo = even old thread, hi = odd)
// Conflict-free both phases (XOR swizzle, verified per half-warp).
__device__ __forceinline__ void transpose64(ull v[NPACK], float* S, int t, int bar) {
    const int p = t >> 1, h = t & 1;
    gbar(bar);                      // previous reads of S complete
    #pragma unroll
    for (int j = 0; j < NPACK; j++) {
        float lo, hi; upk(v[j], lo, hi);
        const int r0 = 2 * j, r1 = 2 * j + 1;
        S[r0 * 64 + 2 * (p ^ (r0 & 31)) + h] = lo;
        S[r1 * 64 + 2 * (p ^ (r1 & 31)) + h] = hi;
    }
    gbar(bar);
    const ull* Su = (const ull*)S;
    #pragma unroll
    for (int j = 0; j < NPACK; j++)
        v[j] = Su[t * 32 + (j ^ (t & 31))];
}

// ---------- main kernel ----------
// Index fields: i[0]=pack bit, i[6:1]=thread t, i[11:7]=reg j.
// y = s1 . H (u . H (s2 . x)) with H applied as:
//   fwht64 (bits {0,11:7}) -> transpose -> fwht64 (bits {6:1})   [FWHT #1]
//   multiply u
//   fwht64 (bits {6:1}) -> transpose -> fwht64 (bits {0,11:7})   [FWHT #2]
__global__ void __launch_bounds__(256, 2)
whvi_kernel(const float* __restrict__ x,
            const float* __restrict__ s1,
            const float* __restrict__ s2,
            float* __restrict__ y) {
    extern __shared__ float sm[];
    float* ex = sm;                          // GROUPS * 4096 floats (64KB)
    ull*   up = (ull*)(sm + GROUPS * 4096);  // 2048 packs (16KB), swizzled

    const int tid = threadIdx.x;

    // Pack u once per CTA: pack for (t,j) = (u[c], u[c+2]),
    // c = (t>>1)*128 + 4*j + (t&1); stored at up[t*32 + (j ^ (t&31))].
    for (int idx = tid; idx < 2048; idx += 256) {
        int t = idx >> 5, jj = idx & 31;
        int j = jj ^ (t & 31);
        int c = (t >> 1) * 128 + 4 * j + (t & 1);
        up[idx] = pk2(g_u[c], g_u[c + 2]);
    }
    __syncthreads();

    const int g = tid >> 6;
    const int t = tid & 63;
    float* exg = ex + g * 4096;
    const int bar = g + 1;

    const float2* __restrict__ x2  = (const float2*)x;
    const float2* __restrict__ s12 = (const float2*)s1;
    const float2* __restrict__ s22 = (const float2*)s2;
    float2* __restrict__ y2 = (float2*)y;

    for (int rb = blockIdx.x; rb < (BROWS / GROUPS); rb += CTAS) {
        const int row = rb * GROUPS + g;
        const float2* __restrict__ xr = x2 + (size_t)row * (D / 2);
        float2* __restrict__ yr = y2 + (size_t)row * (D / 2);

        ull v[NPACK];
        #pragma unroll
        for (int j = 0; j < NPACK; j++) {
            float2 xv = xr[j * 64 + t];
            float2 sv = s22[j * 64 + t];
            v[j] = pmul(pk2(xv.x, xv.y), pk2(sv.x, sv.y));
        }

        fwht64(v);                       // index bits {0, 11:7}
        transpose64(v, exg, t, bar);
        fwht64(v);                       // index bits {6:1}  (FWHT1 done)

        #pragma unroll
        for (int j = 0; j < NPACK; j++)
            v[j] = pmul(v[j], up[t * 32 + (j ^ (t & 31))]);

        fwht64(v);                       // bits {6:1}
        transpose64(v, exg, t, bar);
        fwht64(v);                       // bits {0, 11:7}  (FWHT2 done)

        #pragma unroll
        for (int j = 0; j < NPACK; j++) {
            float2 sv = s12[j * 64 + t];
            ull r = pmul(v[j], pk2(sv.x, sv.y));
            float lo, hi; upk(r, lo, hi);
            yr[j * 64 + t] = make_float2(lo, hi);
        }
    }
}

extern "C" void kernel_launch(void* const* d_in, const int* in_sizes, int n_in,
                              void* d_out, int out_size) {
    const float* x    = (const float*)d_in[0];
    const float* eps  = (const float*)d_in[1];
    const float* s1   = (const float*)d_in[2];
    const float* s2   = (const float*)d_in[3];
    const float* gmu  = (const float*)d_in[4];
    const float* grho = (const float*)d_in[5];
    float* y = (float*)d_out;

    compute_u_kernel<<<D / 256, 256>>>(eps, gmu, grho);

    const size_t smem = GROUPS * 4096 * sizeof(float) + 2048 * sizeof(ull); // 81920 B
    cudaFuncSetAttribute(whvi_kernel,
                         cudaFuncAttributeMaxDynamicSharedMemorySize, (int)smem);
    whvi_kernel<<<CTAS, 256, smem>>>(x, s1, s2, y);
}